// round 2
// baseline (speedup 1.0000x reference)
#include <cuda_runtime.h>

typedef unsigned long long u64;

#define Bsz   4096
#define Tt    512
#define HID   32
#define FOUT  20
#define WARPS 4
#define PAIRS 4                    // f32x2 pairs per warp -> 8 samples/warp
#define SPW   (PAIRS * 2)          // samples per warp
#define SPB   (WARPS * SPW)        // 32 samples per block
#define NBLK  (Bsz / SPB)          // 128 blocks

#define Z1ROWS 34                  // [x0,x1, h1(32)]
#define Z2ROWS 96                  // [h1(32), h2_buf0(32), h2_buf1(32)]

// ---- shared memory layout (in floats, all 16B aligned) ----
#define OW1  0                          // [34][32][4]  L1 weights gate-packed
#define OW2  (OW1 + 34*32*4)            // [64][32][4]  L2 weights (ih2|hh2)
#define OWO  (OW2 + 64*32*4)            // [32][20]     W_out transposed
#define OB1  (OWO + 32*20)              // [32][4]
#define OB2  (OB1 + 32*4)
#define OBO  (OB2 + 32*4)               // [20] (pad to 32)
#define OZ1  (OBO + 32)                 // [WARPS][34][8]
#define OZ2  (OZ1 + WARPS*Z1ROWS*8)     // [WARPS][96][8]
#define SMEM_FLOATS (OZ2 + WARPS*Z2ROWS*8)
#define SMEM_BYTES  (SMEM_FLOATS * 4)

__device__ __forceinline__ u64 pk(float lo, float hi) {
    u64 r; asm("mov.b64 %0, {%1, %2};" : "=l"(r) : "f"(lo), "f"(hi)); return r;
}
__device__ __forceinline__ void upk(u64 v, float& lo, float& hi) {
    asm("mov.b64 {%0, %1}, %2;" : "=f"(lo), "=f"(hi) : "l"(v));
}
__device__ __forceinline__ u64 fma2(u64 a, u64 b, u64 c) {
    u64 d; asm("fma.rn.f32x2 %0, %1, %2, %3;" : "=l"(d) : "l"(a), "l"(b), "l"(c)); return d;
}
__device__ __forceinline__ u64 mul2(u64 a, u64 b) {
    u64 d; asm("mul.rn.f32x2 %0, %1, %2;" : "=l"(d) : "l"(a), "l"(b)); return d;
}
__device__ __forceinline__ float sigmf(float x) {
    return __fdividef(1.f, 1.f + __expf(-x));
}
__device__ __forceinline__ float tanhfast(float x) {
    float a = fabsf(x);
    float e = __expf(-2.f * a);
    float t = __fdividef(1.f - e, 1.f + e);
    return copysignf(t, x);
}

// LSTM epilogue for one f32x2 pair.
__device__ __forceinline__ u64 lstm_epi(u64 ai, u64 af, u64 ag, u64 ao, u64& c) {
    float i0, i1, f0, f1, g0, g1, o0, o1;
    upk(ai, i0, i1); upk(af, f0, f1); upk(ag, g0, g1); upk(ao, o0, o1);
    i0 = sigmf(i0); i1 = sigmf(i1);
    f0 = sigmf(f0); f1 = sigmf(f1);
    g0 = tanhfast(g0); g1 = tanhfast(g1);
    o0 = sigmf(o0); o1 = sigmf(o1);
    u64 ig = mul2(pk(i0, i1), pk(g0, g1));
    c = fma2(pk(f0, f1), c, ig);
    float ca, cb; upk(c, ca, cb);
    return pk(o0 * tanhfast(ca), o1 * tanhfast(cb));
}

__global__ void __launch_bounds__(WARPS * 32, 1)
lstm_seq_kernel(const float* __restrict__ x,
                const float* __restrict__ Wih1, const float* __restrict__ Whh1,
                const float* __restrict__ bih1, const float* __restrict__ bhh1,
                const float* __restrict__ Wih2, const float* __restrict__ Whh2,
                const float* __restrict__ bih2, const float* __restrict__ bhh2,
                const float* __restrict__ Wout, const float* __restrict__ bout,
                float* __restrict__ out)
{
    extern __shared__ float sm[];
    const int tid = threadIdx.x;

    // ---- stage weights (transposed, gate-packed) ----
    for (int idx = tid; idx < 34 * 32; idx += blockDim.x) {
        int k = idx >> 5, j = idx & 31;
        #pragma unroll
        for (int g = 0; g < 4; g++) {
            float v = (k < 2) ? Wih1[(g * 32 + j) * 2 + k]
                              : Whh1[(g * 32 + j) * 32 + (k - 2)];
            sm[OW1 + idx * 4 + g] = v;
        }
    }
    for (int idx = tid; idx < 64 * 32; idx += blockDim.x) {
        int k = idx >> 5, j = idx & 31;
        #pragma unroll
        for (int g = 0; g < 4; g++) {
            float v = (k < 32) ? Wih2[(g * 32 + j) * 32 + k]
                               : Whh2[(g * 32 + j) * 32 + (k - 32)];
            sm[OW2 + idx * 4 + g] = v;
        }
    }
    for (int idx = tid; idx < 32 * 20; idx += blockDim.x) {
        int k = idx / 20, o = idx % 20;
        sm[OWO + idx] = Wout[o * 32 + k];
    }
    for (int idx = tid; idx < 32; idx += blockDim.x) {
        #pragma unroll
        for (int g = 0; g < 4; g++) {
            sm[OB1 + idx * 4 + g] = bih1[g * 32 + idx] + bhh1[g * 32 + idx];
            sm[OB2 + idx * 4 + g] = bih2[g * 32 + idx] + bhh2[g * 32 + idx];
        }
    }
    for (int idx = tid; idx < FOUT; idx += blockDim.x) sm[OBO + idx] = bout[idx];
    for (int idx = tid; idx < WARPS * Z1ROWS * 8; idx += blockDim.x) sm[OZ1 + idx] = 0.f;
    for (int idx = tid; idx < WARPS * Z2ROWS * 8; idx += blockDim.x) sm[OZ2 + idx] = 0.f;
    __syncthreads();

    const int w    = tid >> 5;
    const int lane = tid & 31;
    const int sWarp = blockIdx.x * SPB + w * SPW;

    float* z1 = sm + OZ1 + w * Z1ROWS * 8;   // [34][8]: z1[k*8 + p*2 + half]
    float* z2 = sm + OZ2 + w * Z2ROWS * 8;   // [96][8]: h1 rows 0..31, h2 buf0 32..63, buf1 64..95

    u64 c1[PAIRS], c2[PAIRS];
    #pragma unroll
    for (int p = 0; p < PAIRS; p++) { c1[p] = 0ull; c2[p] = 0ull; }

    // packed biases in registers
    float4 bv1 = *(const float4*)&sm[OB1 + lane * 4];
    float4 bv2 = *(const float4*)&sm[OB2 + lane * 4];
    u64 bb1[4] = { pk(bv1.x,bv1.x), pk(bv1.y,bv1.y), pk(bv1.z,bv1.z), pk(bv1.w,bv1.w) };
    u64 bb2[4] = { pk(bv2.x,bv2.x), pk(bv2.y,bv2.y), pk(bv2.z,bv2.z), pk(bv2.w,bv2.w) };
    const float bo = (lane < FOUT) ? sm[OBO + lane] : 0.f;
    const u64  bod = pk(bo, bo);

    // prefetch x(t=0)
    float2 xv = make_float2(0.f, 0.f);
    if (lane < SPW) xv = ((const float2*)x)[(size_t)(sWarp + lane) * Tt];

    for (int t = 0; t < Tt; t++) {
        const int hbW = t & 1;          // h2 buffer written this step
        const int hbR = hbW ^ 1;        // h2(t-1) buffer (read)
        float* h2r = z2 + (32 + 32 * hbR) * 8;
        float* h2w = z2 + (32 + 32 * hbW) * 8;

        // ---- A: store x_t, prefetch x_{t+1} ----
        if (lane < SPW) {
            z1[lane]     = xv.x;
            z1[8 + lane] = xv.y;
        }
        __syncwarp();
        if (lane < SPW && t + 1 < Tt)
            xv = ((const float2*)x)[(size_t)(sWarp + lane) * Tt + t + 1];

        // ---- C: layer-1 accumulate (k = 0..33) ----
        u64 a0[PAIRS], a1[PAIRS], a2[PAIRS], a3[PAIRS];
        #pragma unroll
        for (int p = 0; p < PAIRS; p++) { a0[p]=bb1[0]; a1[p]=bb1[1]; a2[p]=bb1[2]; a3[p]=bb1[3]; }
        #pragma unroll 2
        for (int k = 0; k < 34; k++) {
            float4 wv = *(const float4*)&sm[OW1 + (k * 32 + lane) * 4];
            u64 w0 = pk(wv.x, wv.x), w1 = pk(wv.y, wv.y);
            u64 w2 = pk(wv.z, wv.z), w3 = pk(wv.w, wv.w);
            ulonglong2 zA = *(const ulonglong2*)&z1[k * 8];
            ulonglong2 zB = *(const ulonglong2*)&z1[k * 8 + 4];
            u64 zp[PAIRS] = { zA.x, zA.y, zB.x, zB.y };
            #pragma unroll
            for (int p = 0; p < PAIRS; p++) {
                a0[p] = fma2(w0, zp[p], a0[p]);
                a1[p] = fma2(w1, zp[p], a1[p]);
                a2[p] = fma2(w2, zp[p], a2[p]);
                a3[p] = fma2(w3, zp[p], a3[p]);
            }
        }

        // ---- D: layer-2 part B (h2(t-1), k = 32..63) -- independent of L1 epi ----
        u64 d0[PAIRS], d1[PAIRS], d2[PAIRS], d3[PAIRS];
        #pragma unroll
        for (int p = 0; p < PAIRS; p++) { d0[p]=bb2[0]; d1[p]=bb2[1]; d2[p]=bb2[2]; d3[p]=bb2[3]; }

        // ---- E: layer-1 epilogue (MUFU) -- interleaves with D below ----
        u64 hp1[PAIRS];
        #pragma unroll
        for (int p = 0; p < PAIRS; p++)
            hp1[p] = lstm_epi(a0[p], a1[p], a2[p], a3[p], c1[p]);

        #pragma unroll 2
        for (int k = 0; k < 32; k++) {
            float4 wv = *(const float4*)&sm[OW2 + ((32 + k) * 32 + lane) * 4];
            u64 w0 = pk(wv.x, wv.x), w1 = pk(wv.y, wv.y);
            u64 w2 = pk(wv.z, wv.z), w3 = pk(wv.w, wv.w);
            ulonglong2 zA = *(const ulonglong2*)&h2r[k * 8];
            ulonglong2 zB = *(const ulonglong2*)&h2r[k * 8 + 4];
            u64 zp[PAIRS] = { zA.x, zA.y, zB.x, zB.y };
            #pragma unroll
            for (int p = 0; p < PAIRS; p++) {
                d0[p] = fma2(w0, zp[p], d0[p]);
                d1[p] = fma2(w1, zp[p], d1[p]);
                d2[p] = fma2(w2, zp[p], d2[p]);
                d3[p] = fma2(w3, zp[p], d3[p]);
            }
        }

        __syncwarp();   // L1 acc reads of z1 h-rows complete before overwrite

        // ---- G: publish h1 -> z1 rows (2+lane), z2 row lane ----
        {
            float4 v0, v1;
            float t0,t1; upk(hp1[0], t0, t1); v0.x=t0; v0.y=t1;
            upk(hp1[1], t0, t1); v0.z=t0; v0.w=t1;
            upk(hp1[2], t0, t1); v1.x=t0; v1.y=t1;
            upk(hp1[3], t0, t1); v1.z=t0; v1.w=t1;
            *(float4*)&z1[(2 + lane) * 8]     = v0;
            *(float4*)&z1[(2 + lane) * 8 + 4] = v1;
            *(float4*)&z2[lane * 8]     = v0;
            *(float4*)&z2[lane * 8 + 4] = v1;
        }
        __syncwarp();   // h1 visible

        // ---- I: layer-2 part A (h1(t), k = 0..31) ----
        #pragma unroll 2
        for (int k = 0; k < 32; k++) {
            float4 wv = *(const float4*)&sm[OW2 + (k * 32 + lane) * 4];
            u64 w0 = pk(wv.x, wv.x), w1 = pk(wv.y, wv.y);
            u64 w2 = pk(wv.z, wv.z), w3 = pk(wv.w, wv.w);
            ulonglong2 zA = *(const ulonglong2*)&z2[k * 8];
            ulonglong2 zB = *(const ulonglong2*)&z2[k * 8 + 4];
            u64 zp[PAIRS] = { zA.x, zA.y, zB.x, zB.y };
            #pragma unroll
            for (int p = 0; p < PAIRS; p++) {
                d0[p] = fma2(w0, zp[p], d0[p]);
                d1[p] = fma2(w1, zp[p], d1[p]);
                d2[p] = fma2(w2, zp[p], d2[p]);
                d3[p] = fma2(w3, zp[p], d3[p]);
            }
        }

        // ---- J: deferred head(t-1) (reads h2r -- not written this step) ----
        // ---- K: layer-2 epilogue (MUFU) -- interleaves with J ----
        u64 hp2[PAIRS];
        #pragma unroll
        for (int p = 0; p < PAIRS; p++)
            hp2[p] = lstm_epi(d0[p], d1[p], d2[p], d3[p], c2[p]);

        if (t > 0 && lane < FOUT) {
            u64 acc[PAIRS];
            #pragma unroll
            for (int p = 0; p < PAIRS; p++) acc[p] = bod;
            #pragma unroll 4
            for (int k = 0; k < 32; k++) {
                float wo = sm[OWO + k * FOUT + lane];
                u64 wd = pk(wo, wo);
                ulonglong2 zA = *(const ulonglong2*)&h2r[k * 8];
                ulonglong2 zB = *(const ulonglong2*)&h2r[k * 8 + 4];
                u64 zp[PAIRS] = { zA.x, zA.y, zB.x, zB.y };
                #pragma unroll
                for (int p = 0; p < PAIRS; p++) acc[p] = fma2(wd, zp[p], acc[p]);
            }
            #pragma unroll
            for (int p = 0; p < PAIRS; p++) {
                float oa, ob; upk(acc[p], oa, ob);
                size_t sa = (size_t)(sWarp + 2 * p);
                out[(sa * Tt + (t - 1)) * FOUT + lane]       = oa;
                out[((sa + 1) * Tt + (t - 1)) * FOUT + lane] = ob;
            }
        }

        // ---- M: publish h2(t) -> write buffer (no one reads it this step) ----
        {
            float4 v0, v1;
            float t0,t1; upk(hp2[0], t0, t1); v0.x=t0; v0.y=t1;
            upk(hp2[1], t0, t1); v0.z=t0; v0.w=t1;
            upk(hp2[2], t0, t1); v1.x=t0; v1.y=t1;
            upk(hp2[3], t0, t1); v1.z=t0; v1.w=t1;
            *(float4*)&h2w[lane * 8]     = v0;
            *(float4*)&h2w[lane * 8 + 4] = v1;
        }
        __syncwarp();   // h2 visible for next iteration's part B / head
    }

    // ---- final head for t = 511 ----
    {
        float* h2r = z2 + (32 + 32 * ((Tt - 1) & 1)) * 8;
        if (lane < FOUT) {
            u64 acc[PAIRS];
            #pragma unroll
            for (int p = 0; p < PAIRS; p++) acc[p] = bod;
            #pragma unroll 4
            for (int k = 0; k < 32; k++) {
                float wo = sm[OWO + k * FOUT + lane];
                u64 wd = pk(wo, wo);
                ulonglong2 zA = *(const ulonglong2*)&h2r[k * 8];
                ulonglong2 zB = *(const ulonglong2*)&h2r[k * 8 + 4];
                u64 zp[PAIRS] = { zA.x, zA.y, zB.x, zB.y };
                #pragma unroll
                for (int p = 0; p < PAIRS; p++) acc[p] = fma2(wd, zp[p], acc[p]);
            }
            #pragma unroll
            for (int p = 0; p < PAIRS; p++) {
                float oa, ob; upk(acc[p], oa, ob);
                size_t sa = (size_t)(sWarp + 2 * p);
                out[(sa * Tt + (Tt - 1)) * FOUT + lane]       = oa;
                out[((sa + 1) * Tt + (Tt - 1)) * FOUT + lane] = ob;
            }
        }
    }
}

extern "C" void kernel_launch(void* const* d_in, const int* in_sizes, int n_in,
                              void* d_out, int out_size) {
    const float* x    = (const float*)d_in[0];
    const float* Wih1 = (const float*)d_in[1];
    const float* Whh1 = (const float*)d_in[2];
    const float* bih1 = (const float*)d_in[3];
    const float* bhh1 = (const float*)d_in[4];
    const float* Wih2 = (const float*)d_in[5];
    const float* Whh2 = (const float*)d_in[6];
    const float* bih2 = (const float*)d_in[7];
    const float* bhh2 = (const float*)d_in[8];
    const float* Wout = (const float*)d_in[9];
    const float* bout = (const float*)d_in[10];
    float* out = (float*)d_out;

    cudaFuncSetAttribute(lstm_seq_kernel,
                         cudaFuncAttributeMaxDynamicSharedMemorySize, SMEM_BYTES);
    lstm_seq_kernel<<<NBLK, WARPS * 32, SMEM_BYTES>>>(
        x, Wih1, Whh1, bih1, bhh1, Wih2, Whh2, bih2, bhh2, Wout, bout, out);
}

// round 4
// speedup vs baseline: 1.2083x; 1.2083x over previous
#include <cuda_runtime.h>

typedef unsigned long long u64;

#define Bsz   4096
#define Tt    512
#define FOUT  20
#define PAIRS 4                     // f32x2 pairs per sample-group -> 8 samples
#define SPG   (PAIRS * 2)           // samples per group (2 warps)
#define GRPS  4                     // groups per block
#define SPB   (GRPS * SPG)          // 32 samples per block
#define NBLK  (Bsz / SPB)           // 128 blocks

// ---- shared layout (floats) ----
#define OW1   0                         // [34][64 wlane][2]  L1 gate-pair weights
#define OW2   (OW1 + 34*128)            // [64][64][2]
#define OWO   (OW2 + 64*128)            // [32][20]
#define OB1   (OWO + 640)               // [64][2]
#define OB2   (OB1 + 128)               // [64][2]
#define OBO   (OB2 + 128)               // [20] pad 32
#define OZ1   (OBO + 32)                // per group: x[2buf][2row][8] + h1[2buf][32][8]
#define Z1G   (32 + 512)                // 544
#define OZ2   (OZ1 + GRPS*Z1G)          // per group: h1cur[32][8] + h2[2buf][32][8]
#define Z2G   (256 + 512)               // 768
#define SMEM_FLOATS (OZ2 + GRPS*Z2G)
#define SMEM_BYTES  (SMEM_FLOATS * 4)

__device__ __forceinline__ u64 pk(float lo, float hi) {
    u64 r; asm("mov.b64 %0, {%1, %2};" : "=l"(r) : "f"(lo), "f"(hi)); return r;
}
__device__ __forceinline__ void upk(u64 v, float& lo, float& hi) {
    asm("mov.b64 {%0, %1}, %2;" : "=f"(lo), "=f"(hi) : "l"(v));
}
__device__ __forceinline__ u64 fma2(u64 a, u64 b, u64 c) {
    u64 d; asm("fma.rn.f32x2 %0, %1, %2, %3;" : "=l"(d) : "l"(a), "l"(b), "l"(c)); return d;
}
__device__ __forceinline__ u64 mul2(u64 a, u64 b) {
    u64 d; asm("mul.rn.f32x2 %0, %1, %2;" : "=l"(d) : "l"(a), "l"(b)); return d;
}
__device__ __forceinline__ float sigmf(float x) {
    return __fdividef(1.f, 1.f + __expf(-x));
}
__device__ __forceinline__ u64 shfl_xor64(u64 v, int m) {
    float lo, hi; upk(v, lo, hi);
    lo = __shfl_xor_sync(0xffffffffu, lo, m);
    hi = __shfl_xor_sync(0xffffffffu, hi, m);
    return pk(lo, hi);
}

// Gate-split LSTM epilogue for one pair.
// gp0 lanes: av = gate-i preact, bv = gate-g. gp1 lanes: av = f, bv = o.
// gp0: vB = tanh(b) via 2*sig(2b)-1; gp1: vB = sig(b).
// Returns h (valid on gp1 lanes), updates c (valid on gp1 lanes).
__device__ __forceinline__ u64 epi(u64 av, u64 bv, u64& c,
                                   float mB, float kM, float kA) {
    float a0, a1, b0, b1;
    upk(av, a0, a1); upk(bv, b0, b1);
    float sa0 = sigmf(a0), sa1 = sigmf(a1);              // gp0: sig(i); gp1: sig(f)
    float s0 = sigmf(mB * b0), s1 = sigmf(mB * b1);
    float vb0 = fmaf(kM, s0, kA), vb1 = fmaf(kM, s1, kA); // gp0: tanh(g); gp1: sig(o)
    u64 sA = pk(sa0, sa1), vB = pk(vb0, vb1);
    u64 ig = shfl_xor64(mul2(sA, vB), 16);               // i*g from gp0 -> gp1
    c = fma2(sA, c, ig);                                 // gp1: c = f*c + i*g
    float c0, c1; upk(c, c0, c1);
    float tc0 = fmaf(2.f, sigmf(2.f * c0), -1.f);        // tanh(c)
    float tc1 = fmaf(2.f, sigmf(2.f * c1), -1.f);
    return mul2(vB, pk(tc0, tc1));                       // gp1: h = sig(o)*tanh(c)
}

__global__ void __launch_bounds__(256, 1)
lstm_seq_kernel(const float* __restrict__ x,
                const float* __restrict__ Wih1, const float* __restrict__ Whh1,
                const float* __restrict__ bih1, const float* __restrict__ bhh1,
                const float* __restrict__ Wih2, const float* __restrict__ Whh2,
                const float* __restrict__ bih2, const float* __restrict__ bhh2,
                const float* __restrict__ Wout, const float* __restrict__ bout,
                float* __restrict__ out)
{
    extern __shared__ float sm[];
    const int tid = threadIdx.x;

    // ---- stage weights. wlane r = ws*32 + l; l = (gp<<4)|j; unit u = ws*16 + j.
    // gp0 owns gates (i,g) = (0,2); gp1 owns (f,o) = (1,3).
    for (int idx = tid; idx < 34 * 64; idx += 256) {
        int k = idx >> 6, r = idx & 63;
        int ws = r >> 5, l = r & 31, j = l & 15, gpp = l >> 4;
        int u = ws * 16 + j;
        float vA = (k < 2) ? Wih1[(gpp * 32 + u) * 2 + k]
                           : Whh1[(gpp * 32 + u) * 32 + (k - 2)];
        float vB = (k < 2) ? Wih1[((gpp + 2) * 32 + u) * 2 + k]
                           : Whh1[((gpp + 2) * 32 + u) * 32 + (k - 2)];
        sm[OW1 + k * 128 + r * 2]     = vA;
        sm[OW1 + k * 128 + r * 2 + 1] = vB;
    }
    for (int idx = tid; idx < 64 * 64; idx += 256) {
        int k = idx >> 6, r = idx & 63;
        int ws = r >> 5, l = r & 31, j = l & 15, gpp = l >> 4;
        int u = ws * 16 + j;
        float vA = (k < 32) ? Wih2[(gpp * 32 + u) * 32 + k]
                            : Whh2[(gpp * 32 + u) * 32 + (k - 32)];
        float vB = (k < 32) ? Wih2[((gpp + 2) * 32 + u) * 32 + k]
                            : Whh2[((gpp + 2) * 32 + u) * 32 + (k - 32)];
        sm[OW2 + k * 128 + r * 2]     = vA;
        sm[OW2 + k * 128 + r * 2 + 1] = vB;
    }
    for (int idx = tid; idx < 32 * 20; idx += 256) {
        int k = idx / 20, o = idx % 20;
        sm[OWO + idx] = Wout[o * 32 + k];
    }
    for (int idx = tid; idx < 64; idx += 256) {
        int ws = idx >> 5, l = idx & 31, j = l & 15, gpp = l >> 4;
        int u = ws * 16 + j;
        sm[OB1 + idx * 2]     = bih1[gpp * 32 + u] + bhh1[gpp * 32 + u];
        sm[OB1 + idx * 2 + 1] = bih1[(gpp + 2) * 32 + u] + bhh1[(gpp + 2) * 32 + u];
        sm[OB2 + idx * 2]     = bih2[gpp * 32 + u] + bhh2[gpp * 32 + u];
        sm[OB2 + idx * 2 + 1] = bih2[(gpp + 2) * 32 + u] + bhh2[(gpp + 2) * 32 + u];
    }
    for (int idx = tid; idx < FOUT; idx += 256) sm[OBO + idx] = bout[idx];
    // zero h buffers (x buffers fully written before use)
    for (int g = 0; g < GRPS; g++) {
        for (int idx = tid; idx < 512; idx += 256) sm[OZ1 + g * Z1G + 32 + idx] = 0.f;
        for (int idx = tid; idx < Z2G; idx += 256) sm[OZ2 + g * Z2G + idx] = 0.f;
    }

    const int w     = tid >> 5;
    const int lane  = tid & 31;
    const int grp   = w >> 1;
    const int wsub  = w & 1;
    const int j     = lane & 15;
    const int gp    = lane >> 4;
    const int u     = wsub * 16 + j;        // hidden unit this thread owns (gp1 lanes)
    const int wlane = wsub * 32 + lane;     // weight column index
    const int sBase = blockIdx.x * SPB + grp * SPG;

    float* z1x  = sm + OZ1 + grp * Z1G;      // [2buf][2row][8]
    float* z1h  = z1x + 32;                  // [2buf][32][8]
    float* z2h1 = sm + OZ2 + grp * Z2G;      // [32][8]
    float* z2h2 = z2h1 + 256;                // [2buf][32][8]

    const float mB = gp ? 1.f : 2.f;
    const float kM = gp ? 1.f : 2.f;
    const float kA = gp ? 0.f : -1.f;

    const float2* x2 = (const float2*)x;
    float2 xv = make_float2(0.f, 0.f);
    if (wsub == 0 && lane < 8) {
        float2 x0 = x2[(size_t)(sBase + lane) * Tt];
        int p = lane >> 1, hf = lane & 1;
        z1x[p * 2 + hf]     = x0.x;          // buf0 row0
        z1x[8 + p * 2 + hf] = x0.y;          // buf0 row1
        xv = x2[(size_t)(sBase + lane) * Tt + 1];
    }
    __syncthreads();

    // packed biases
    float2 b1v = *(const float2*)&sm[OB1 + wlane * 2];
    float2 b2v = *(const float2*)&sm[OB2 + wlane * 2];
    const u64 b1A = pk(b1v.x, b1v.x), b1B = pk(b1v.y, b1v.y);
    const u64 b2A = pk(b2v.x, b2v.x), b2B = pk(b2v.y, b2v.y);
    const float bo = (lane < FOUT) ? sm[OBO + lane] : 0.f;
    const u64  bod = pk(bo, bo);

    u64 c1[PAIRS], c2[PAIRS];
    #pragma unroll
    for (int p = 0; p < PAIRS; p++) { c1[p] = 0ull; c2[p] = 0ull; }

    for (int t = 0; t < Tt; t++) {
        const int par = t & 1;
        const float* xrd  = z1x + par * 16;
        const float* h1rd = z1h + (par ^ 1) * 256;
        float*       h1wr = z1h + par * 256;
        const float* h2rd = z2h2 + (par ^ 1) * 256;
        float*       h2wr = z2h2 + par * 256;

        // ---- 1. layer-1 accumulate ----
        u64 aA[PAIRS], aB[PAIRS];
        #pragma unroll
        for (int p = 0; p < PAIRS; p++) { aA[p] = b1A; aB[p] = b1B; }
        #pragma unroll
        for (int k = 0; k < 2; k++) {
            float2 wv = *(const float2*)&sm[OW1 + k * 128 + wlane * 2];
            u64 wA = pk(wv.x, wv.x), wB = pk(wv.y, wv.y);
            ulonglong2 zA = *(const ulonglong2*)&xrd[k * 8];
            ulonglong2 zB = *(const ulonglong2*)&xrd[k * 8 + 4];
            u64 zp[PAIRS] = { zA.x, zA.y, zB.x, zB.y };
            #pragma unroll
            for (int p = 0; p < PAIRS; p++) {
                aA[p] = fma2(wA, zp[p], aA[p]);
                aB[p] = fma2(wB, zp[p], aB[p]);
            }
        }
        #pragma unroll 8
        for (int k = 0; k < 32; k++) {
            float2 wv = *(const float2*)&sm[OW1 + (k + 2) * 128 + wlane * 2];
            u64 wA = pk(wv.x, wv.x), wB = pk(wv.y, wv.y);
            ulonglong2 zA = *(const ulonglong2*)&h1rd[k * 8];
            ulonglong2 zB = *(const ulonglong2*)&h1rd[k * 8 + 4];
            u64 zp[PAIRS] = { zA.x, zA.y, zB.x, zB.y };
            #pragma unroll
            for (int p = 0; p < PAIRS; p++) {
                aA[p] = fma2(wA, zp[p], aA[p]);
                aB[p] = fma2(wB, zp[p], aB[p]);
            }
        }

        // ---- 2. layer-2 part B: h2(t-1), weight rows 32..63 ----
        u64 dA[PAIRS], dB[PAIRS];
        #pragma unroll
        for (int p = 0; p < PAIRS; p++) { dA[p] = b2A; dB[p] = b2B; }
        #pragma unroll 8
        for (int k = 0; k < 32; k++) {
            float2 wv = *(const float2*)&sm[OW2 + (32 + k) * 128 + wlane * 2];
            u64 wA = pk(wv.x, wv.x), wB = pk(wv.y, wv.y);
            ulonglong2 zA = *(const ulonglong2*)&h2rd[k * 8];
            ulonglong2 zB = *(const ulonglong2*)&h2rd[k * 8 + 4];
            u64 zp[PAIRS] = { zA.x, zA.y, zB.x, zB.y };
            #pragma unroll
            for (int p = 0; p < PAIRS; p++) {
                dA[p] = fma2(wA, zp[p], dA[p]);
                dB[p] = fma2(wB, zp[p], dB[p]);
            }
        }

        // ---- 3. layer-1 epilogue ----
        u64 h1p[PAIRS];
        #pragma unroll
        for (int p = 0; p < PAIRS; p++)
            h1p[p] = epi(aA[p], aB[p], c1[p], mB, kM, kA);

        // ---- 4. store x(t+1), prefetch x(t+2), publish h1 ----
        if (wsub == 0 && lane < 8) {
            int p = lane >> 1, hf = lane & 1;
            float* xwr = z1x + (par ^ 1) * 16;
            xwr[p * 2 + hf]     = xv.x;
            xwr[8 + p * 2 + hf] = xv.y;
            if (t + 2 < Tt) xv = x2[(size_t)(sBase + lane) * Tt + t + 2];
        }
        if (gp) {
            float4 v0, v1; float e0, e1;
            upk(h1p[0], e0, e1); v0.x = e0; v0.y = e1;
            upk(h1p[1], e0, e1); v0.z = e0; v0.w = e1;
            upk(h1p[2], e0, e1); v1.x = e0; v1.y = e1;
            upk(h1p[3], e0, e1); v1.z = e0; v1.w = e1;
            *(float4*)&h1wr[u * 8]     = v0;
            *(float4*)&h1wr[u * 8 + 4] = v1;
            *(float4*)&z2h1[u * 8]     = v0;
            *(float4*)&z2h1[u * 8 + 4] = v1;
        }
        __syncthreads();

        // ---- 5. layer-2 part A: h1(t), weight rows 0..31 ----
        #pragma unroll 8
        for (int k = 0; k < 32; k++) {
            float2 wv = *(const float2*)&sm[OW2 + k * 128 + wlane * 2];
            u64 wA = pk(wv.x, wv.x), wB = pk(wv.y, wv.y);
            ulonglong2 zA = *(const ulonglong2*)&z2h1[k * 8];
            ulonglong2 zB = *(const ulonglong2*)&z2h1[k * 8 + 4];
            u64 zp[PAIRS] = { zA.x, zA.y, zB.x, zB.y };
            #pragma unroll
            for (int p = 0; p < PAIRS; p++) {
                dA[p] = fma2(wA, zp[p], dA[p]);
                dB[p] = fma2(wB, zp[p], dB[p]);
            }
        }

        // ---- 6. layer-2 epilogue ----
        u64 h2p[PAIRS];
        #pragma unroll
        for (int p = 0; p < PAIRS; p++)
            h2p[p] = epi(dA[p], dB[p], c2[p], mB, kM, kA);

        // ---- 7. deferred head(t-1): each warp does 2 of the group's 4 pairs ----
        if (t > 0 && lane < FOUT) {
            const int pO = wsub * 2;
            u64 acc0 = bod, acc1 = bod;
            #pragma unroll 8
            for (int k = 0; k < 32; k++) {
                float wo = sm[OWO + k * FOUT + lane];
                u64 wd = pk(wo, wo);
                ulonglong2 zz = *(const ulonglong2*)&h2rd[k * 8 + pO * 2];
                acc0 = fma2(wd, zz.x, acc0);
                acc1 = fma2(wd, zz.y, acc1);
            }
            float o0, o1;
            size_t rbase = ((size_t)(sBase + 2 * pO) * Tt + (t - 1)) * FOUT + lane;
            upk(acc0, o0, o1);
            out[rbase]             = o0;
            out[rbase + Tt * FOUT] = o1;
            upk(acc1, o0, o1);
            out[rbase + 2 * Tt * FOUT] = o0;
            out[rbase + 3 * Tt * FOUT] = o1;
        }

        // ---- 8. publish h2 ----
        if (gp) {
            float4 v0, v1; float e0, e1;
            upk(h2p[0], e0, e1); v0.x = e0; v0.y = e1;
            upk(h2p[1], e0, e1); v0.z = e0; v0.w = e1;
            upk(h2p[2], e0, e1); v1.x = e0; v1.y = e1;
            upk(h2p[3], e0, e1); v1.z = e0; v1.w = e1;
            *(float4*)&h2wr[u * 8]     = v0;
            *(float4*)&h2wr[u * 8 + 4] = v1;
        }
        __syncthreads();
    }

    // ---- final head: t = Tt-1 ----
    {
        const float* hr = z2h2 + ((Tt - 1) & 1) * 256;
        if (lane < FOUT) {
            const int pO = wsub * 2;
            u64 acc0 = bod, acc1 = bod;
            #pragma unroll 8
            for (int k = 0; k < 32; k++) {
                float wo = sm[OWO + k * FOUT + lane];
                u64 wd = pk(wo, wo);
                ulonglong2 zz = *(const ulonglong2*)&hr[k * 8 + pO * 2];
                acc0 = fma2(wd, zz.x, acc0);
                acc1 = fma2(wd, zz.y, acc1);
            }
            float o0, o1;
            size_t rbase = ((size_t)(sBase + 2 * pO) * Tt + (Tt - 1)) * FOUT + lane;
            upk(acc0, o0, o1);
            out[rbase]             = o0;
            out[rbase + Tt * FOUT] = o1;
            upk(acc1, o0, o1);
            out[rbase + 2 * Tt * FOUT] = o0;
            out[rbase + 3 * Tt * FOUT] = o1;
        }
    }
}

extern "C" void kernel_launch(void* const* d_in, const int* in_sizes, int n_in,
                              void* d_out, int out_size) {
    const float* x    = (const float*)d_in[0];
    const float* Wih1 = (const float*)d_in[1];
    const float* Whh1 = (const float*)d_in[2];
    const float* bih1 = (const float*)d_in[3];
    const float* bhh1 = (const float*)d_in[4];
    const float* Wih2 = (const float*)d_in[5];
    const float* Whh2 = (const float*)d_in[6];
    const float* bih2 = (const float*)d_in[7];
    const float* bhh2 = (const float*)d_in[8];
    const float* Wout = (const float*)d_in[9];
    const float* bout = (const float*)d_in[10];
    float* out = (float*)d_out;

    cudaFuncSetAttribute(lstm_seq_kernel,
                         cudaFuncAttributeMaxDynamicSharedMemorySize, SMEM_BYTES);
    lstm_seq_kernel<<<NBLK, 256, SMEM_BYTES>>>(
        x, Wih1, Whh1, bih1, bhh1, Wih2, Whh2, bih2, bhh2, Wout, bout, out);
}

// round 5
// speedup vs baseline: 1.2741x; 1.0545x over previous
#include <cuda_runtime.h>

typedef unsigned long long u64;

#define Bsz   4096
#define Tt    512
#define FOUT  20
#define NBLK  128
// 8 warps/block = 4 groups x 2 warps; group owns 8 samples (4 f32x2 pairs).
// lane = (ph, j): ph = lane>>4 selects pair-half {0,1}, j = lane&15;
// unit u = wsub*16 + j. Lane owns all 4 gates of unit u for pairs {2ph, 2ph+1}.

// ---- shared layout (floats) ----
#define OW1   0                         // [34][32 units][4 gates]
#define OW2   (OW1 + 34*128)            // [64][32][4]
#define OWO   (OW2 + 64*128)            // [32][20]
#define OB1   (OWO + 640)               // [32][4]
#define OB2   (OB1 + 128)               // [32][4]
#define OBO   (OB2 + 128)               // [20] pad 32
#define OZ1   (OBO + 32)                // per group: x[2buf][2row][8] + h1[2buf][32][8]
#define Z1G   (32 + 512)
#define OZ2   (OZ1 + 4*Z1G)             // per group: h1cur[32][8] + h2[2buf][32][8]
#define Z2G   (256 + 512)
#define SMEM_FLOATS (OZ2 + 4*Z2G)
#define SMEM_BYTES  (SMEM_FLOATS * 4)

__device__ __forceinline__ u64 pk(float lo, float hi) {
    u64 r; asm("mov.b64 %0, {%1, %2};" : "=l"(r) : "f"(lo), "f"(hi)); return r;
}
__device__ __forceinline__ void upk(u64 v, float& lo, float& hi) {
    asm("mov.b64 {%0, %1}, %2;" : "=f"(lo), "=f"(hi) : "l"(v));
}
__device__ __forceinline__ u64 fma2(u64 a, u64 b, u64 c) {
    u64 d; asm("fma.rn.f32x2 %0, %1, %2, %3;" : "=l"(d) : "l"(a), "l"(b), "l"(c)); return d;
}
__device__ __forceinline__ u64 mul2(u64 a, u64 b) {
    u64 d; asm("mul.rn.f32x2 %0, %1, %2;" : "=l"(d) : "l"(a), "l"(b)); return d;
}
__device__ __forceinline__ float sigmf(float x) {
    return __fdividef(1.f, 1.f + __expf(-x));
}

// Fully lane-local LSTM epilogue for one f32x2 pair (2 samples).
__device__ __forceinline__ u64 lstm_epi(u64 ai, u64 af, u64 ag, u64 ao, u64& c) {
    float i0,i1,f0,f1,g0,g1,o0,o1;
    upk(ai,i0,i1); upk(af,f0,f1); upk(ag,g0,g1); upk(ao,o0,o1);
    i0 = sigmf(i0); i1 = sigmf(i1);
    f0 = sigmf(f0); f1 = sigmf(f1);
    g0 = fmaf(2.f, sigmf(2.f*g0), -1.f);   // tanh
    g1 = fmaf(2.f, sigmf(2.f*g1), -1.f);
    o0 = sigmf(o0); o1 = sigmf(o1);
    u64 ig = mul2(pk(i0,i1), pk(g0,g1));
    c = fma2(pk(f0,f1), c, ig);
    float c0,c1; upk(c,c0,c1);
    float t0 = fmaf(2.f, sigmf(2.f*c0), -1.f);
    float t1 = fmaf(2.f, sigmf(2.f*c1), -1.f);
    return mul2(pk(o0,o1), pk(t0,t1));
}

__global__ void __launch_bounds__(256, 1)
lstm_seq_kernel(const float* __restrict__ x,
                const float* __restrict__ Wih1, const float* __restrict__ Whh1,
                const float* __restrict__ bih1, const float* __restrict__ bhh1,
                const float* __restrict__ Wih2, const float* __restrict__ Whh2,
                const float* __restrict__ bih2, const float* __restrict__ bhh2,
                const float* __restrict__ Wout, const float* __restrict__ bout,
                float* __restrict__ out)
{
    extern __shared__ float sm[];
    const int tid = threadIdx.x;

    // ---- stage weights gate-packed: sm[OW1 + (k*32+u)*4 + g] = W1[g*32+u][k]
    for (int idx = tid; idx < 34 * 32; idx += 256) {
        int k = idx >> 5, uu = idx & 31;
        #pragma unroll
        for (int g = 0; g < 4; g++) {
            float v = (k < 2) ? Wih1[(g * 32 + uu) * 2 + k]
                              : Whh1[(g * 32 + uu) * 32 + (k - 2)];
            sm[OW1 + idx * 4 + g] = v;
        }
    }
    for (int idx = tid; idx < 64 * 32; idx += 256) {
        int k = idx >> 5, uu = idx & 31;
        #pragma unroll
        for (int g = 0; g < 4; g++) {
            float v = (k < 32) ? Wih2[(g * 32 + uu) * 32 + k]
                               : Whh2[(g * 32 + uu) * 32 + (k - 32)];
            sm[OW2 + idx * 4 + g] = v;
        }
    }
    for (int idx = tid; idx < 32 * 20; idx += 256) {
        int k = idx / 20, o = idx % 20;
        sm[OWO + idx] = Wout[o * 32 + k];
    }
    for (int idx = tid; idx < 32; idx += 256) {
        #pragma unroll
        for (int g = 0; g < 4; g++) {
            sm[OB1 + idx * 4 + g] = bih1[g * 32 + idx] + bhh1[g * 32 + idx];
            sm[OB2 + idx * 4 + g] = bih2[g * 32 + idx] + bhh2[g * 32 + idx];
        }
    }
    for (int idx = tid; idx < FOUT; idx += 256) sm[OBO + idx] = bout[idx];
    for (int g = 0; g < 4; g++) {
        for (int idx = tid; idx < 512; idx += 256) sm[OZ1 + g * Z1G + 32 + idx] = 0.f;
        for (int idx = tid; idx < Z2G; idx += 256) sm[OZ2 + g * Z2G + idx] = 0.f;
    }

    const int w    = tid >> 5;
    const int lane = tid & 31;
    const int grp  = w >> 1;
    const int wsub = w & 1;
    const int j    = lane & 15;
    const int ph   = lane >> 4;           // pair-half: pairs {2ph, 2ph+1}
    const int u    = wsub * 16 + j;       // hidden unit owned by this lane
    const int sBase = blockIdx.x * 32 + grp * 8;

    float* z1x  = sm + OZ1 + grp * Z1G;    // [2buf][2row][8]
    float* z1h  = z1x + 32;                // [2buf][32][8]
    float* z2h1 = sm + OZ2 + grp * Z2G;    // [32][8]
    float* z2h2 = z2h1 + 256;              // [2buf][32][8]

    const float2* x2 = (const float2*)x;
    float2 xv = make_float2(0.f, 0.f);
    if (wsub == 0 && lane < 8) {
        float2 x0 = x2[(size_t)(sBase + lane) * Tt];
        int p = lane >> 1, hf = lane & 1;
        z1x[p * 2 + hf]     = x0.x;
        z1x[8 + p * 2 + hf] = x0.y;
        xv = x2[(size_t)(sBase + lane) * Tt + 1];
    }
    __syncthreads();

    // biases (broadcast read once)
    float4 bv1 = *(const float4*)&sm[OB1 + u * 4];
    float4 bv2 = *(const float4*)&sm[OB2 + u * 4];
    const u64 b1g[4] = { pk(bv1.x,bv1.x), pk(bv1.y,bv1.y), pk(bv1.z,bv1.z), pk(bv1.w,bv1.w) };
    const u64 b2g[4] = { pk(bv2.x,bv2.x), pk(bv2.y,bv2.y), pk(bv2.z,bv2.z), pk(bv2.w,bv2.w) };
    const float bo = (lane < FOUT) ? sm[OBO + lane] : 0.f;
    const u64  bod = pk(bo, bo);

    u64 c1[2] = {0ull, 0ull}, c2[2] = {0ull, 0ull};

    for (int t = 0; t < Tt; t++) {
        const int par = t & 1;
        const float* xrd  = z1x + par * 16;
        const float* h1rd = z1h + (par ^ 1) * 256;
        float*       h1wr = z1h + par * 256;
        const float* h2rd = z2h2 + (par ^ 1) * 256;
        float*       h2wr = z2h2 + par * 256;

        // ---- 1. layer-1 accumulate (4 gates x 2 local pairs) ----
        u64 a0[2], a1[2], a2[2], a3[2];
        #pragma unroll
        for (int p = 0; p < 2; p++) { a0[p]=b1g[0]; a1[p]=b1g[1]; a2[p]=b1g[2]; a3[p]=b1g[3]; }
        #pragma unroll
        for (int k = 0; k < 2; k++) {
            float4 wv = *(const float4*)&sm[OW1 + (k * 32 + u) * 4];
            u64 w0=pk(wv.x,wv.x), w1=pk(wv.y,wv.y), w2=pk(wv.z,wv.z), w3=pk(wv.w,wv.w);
            ulonglong2 zz = *(const ulonglong2*)&xrd[k * 8 + ph * 4];
            u64 zp[2] = { zz.x, zz.y };
            #pragma unroll
            for (int p = 0; p < 2; p++) {
                a0[p]=fma2(w0,zp[p],a0[p]); a1[p]=fma2(w1,zp[p],a1[p]);
                a2[p]=fma2(w2,zp[p],a2[p]); a3[p]=fma2(w3,zp[p],a3[p]);
            }
        }
        #pragma unroll 8
        for (int k = 0; k < 32; k++) {
            float4 wv = *(const float4*)&sm[OW1 + ((k + 2) * 32 + u) * 4];
            u64 w0=pk(wv.x,wv.x), w1=pk(wv.y,wv.y), w2=pk(wv.z,wv.z), w3=pk(wv.w,wv.w);
            ulonglong2 zz = *(const ulonglong2*)&h1rd[k * 8 + ph * 4];
            u64 zp[2] = { zz.x, zz.y };
            #pragma unroll
            for (int p = 0; p < 2; p++) {
                a0[p]=fma2(w0,zp[p],a0[p]); a1[p]=fma2(w1,zp[p],a1[p]);
                a2[p]=fma2(w2,zp[p],a2[p]); a3[p]=fma2(w3,zp[p],a3[p]);
            }
        }

        // ---- 2. layer-2 part B: h2(t-1), weight rows 32..63 ----
        u64 d0[2], d1[2], d2[2], d3[2];
        #pragma unroll
        for (int p = 0; p < 2; p++) { d0[p]=b2g[0]; d1[p]=b2g[1]; d2[p]=b2g[2]; d3[p]=b2g[3]; }
        #pragma unroll 8
        for (int k = 0; k < 32; k++) {
            float4 wv = *(const float4*)&sm[OW2 + ((32 + k) * 32 + u) * 4];
            u64 w0=pk(wv.x,wv.x), w1=pk(wv.y,wv.y), w2=pk(wv.z,wv.z), w3=pk(wv.w,wv.w);
            ulonglong2 zz = *(const ulonglong2*)&h2rd[k * 8 + ph * 4];
            u64 zp[2] = { zz.x, zz.y };
            #pragma unroll
            for (int p = 0; p < 2; p++) {
                d0[p]=fma2(w0,zp[p],d0[p]); d1[p]=fma2(w1,zp[p],d1[p]);
                d2[p]=fma2(w2,zp[p],d2[p]); d3[p]=fma2(w3,zp[p],d3[p]);
            }
        }

        // ---- 3. layer-1 epilogue (lane-local) ----
        u64 h1p0 = lstm_epi(a0[0], a1[0], a2[0], a3[0], c1[0]);
        u64 h1p1 = lstm_epi(a0[1], a1[1], a2[1], a3[1], c1[1]);

        // ---- 4. stage x(t+1), prefetch x(t+2), publish h1 ----
        if (wsub == 0 && lane < 8) {
            int p = lane >> 1, hf = lane & 1;
            float* xwr = z1x + (par ^ 1) * 16;
            xwr[p * 2 + hf]     = xv.x;
            xwr[8 + p * 2 + hf] = xv.y;
            if (t + 2 < Tt) xv = x2[(size_t)(sBase + lane) * Tt + t + 2];
        }
        {
            float4 hv; upk(h1p0, hv.x, hv.y); upk(h1p1, hv.z, hv.w);
            *(float4*)&h1wr[u * 8 + ph * 4] = hv;
            *(float4*)&z2h1[u * 8 + ph * 4] = hv;
        }
        __syncthreads();

        // ---- 5. layer-2 part A: h1(t), weight rows 0..31 ----
        #pragma unroll 8
        for (int k = 0; k < 32; k++) {
            float4 wv = *(const float4*)&sm[OW2 + (k * 32 + u) * 4];
            u64 w0=pk(wv.x,wv.x), w1=pk(wv.y,wv.y), w2=pk(wv.z,wv.z), w3=pk(wv.w,wv.w);
            ulonglong2 zz = *(const ulonglong2*)&z2h1[k * 8 + ph * 4];
            u64 zp[2] = { zz.x, zz.y };
            #pragma unroll
            for (int p = 0; p < 2; p++) {
                d0[p]=fma2(w0,zp[p],d0[p]); d1[p]=fma2(w1,zp[p],d1[p]);
                d2[p]=fma2(w2,zp[p],d2[p]); d3[p]=fma2(w3,zp[p],d3[p]);
            }
        }

        // ---- 6. layer-2 epilogue ----
        u64 h2p0 = lstm_epi(d0[0], d1[0], d2[0], d3[0], c2[0]);
        u64 h2p1 = lstm_epi(d0[1], d1[1], d2[1], d3[1], c2[1]);

        // ---- 7. deferred head(t-1): each warp handles 2 of the 4 pairs ----
        if (t > 0 && lane < FOUT) {
            const int pO = wsub * 2;
            u64 acc0 = bod, acc1 = bod;
            #pragma unroll 8
            for (int k = 0; k < 32; k++) {
                float wo = sm[OWO + k * FOUT + lane];
                u64 wd = pk(wo, wo);
                ulonglong2 zz = *(const ulonglong2*)&h2rd[k * 8 + pO * 2];
                acc0 = fma2(wd, zz.x, acc0);
                acc1 = fma2(wd, zz.y, acc1);
            }
            float o0, o1;
            size_t rbase = ((size_t)(sBase + 2 * pO) * Tt + (t - 1)) * FOUT + lane;
            upk(acc0, o0, o1);
            out[rbase]             = o0;
            out[rbase + Tt * FOUT] = o1;
            upk(acc1, o0, o1);
            out[rbase + 2 * Tt * FOUT] = o0;
            out[rbase + 3 * Tt * FOUT] = o1;
        }

        // ---- 8. publish h2 ----
        {
            float4 hv; upk(h2p0, hv.x, hv.y); upk(h2p1, hv.z, hv.w);
            *(float4*)&h2wr[u * 8 + ph * 4] = hv;
        }
        __syncthreads();
    }

    // ---- final head: t = Tt-1 ----
    {
        const float* hr = z2h2 + ((Tt - 1) & 1) * 256;
        if (lane < FOUT) {
            const int pO = wsub * 2;
            u64 acc0 = bod, acc1 = bod;
            #pragma unroll 8
            for (int k = 0; k < 32; k++) {
                float wo = sm[OWO + k * FOUT + lane];
                u64 wd = pk(wo, wo);
                ulonglong2 zz = *(const ulonglong2*)&hr[k * 8 + pO * 2];
                acc0 = fma2(wd, zz.x, acc0);
                acc1 = fma2(wd, zz.y, acc1);
            }
            float o0, o1;
            size_t rbase = ((size_t)(sBase + 2 * pO) * Tt + (Tt - 1)) * FOUT + lane;
            upk(acc0, o0, o1);
            out[rbase]             = o0;
            out[rbase + Tt * FOUT] = o1;
            upk(acc1, o0, o1);
            out[rbase + 2 * Tt * FOUT] = o0;
            out[rbase + 3 * Tt * FOUT] = o1;
        }
    }
}

extern "C" void kernel_launch(void* const* d_in, const int* in_sizes, int n_in,
                              void* d_out, int out_size) {
    const float* x    = (const float*)d_in[0];
    const float* Wih1 = (const float*)d_in[1];
    const float* Whh1 = (const float*)d_in[2];
    const float* bih1 = (const float*)d_in[3];
    const float* bhh1 = (const float*)d_in[4];
    const float* Wih2 = (const float*)d_in[5];
    const float* Whh2 = (const float*)d_in[6];
    const float* bih2 = (const float*)d_in[7];
    const float* bhh2 = (const float*)d_in[8];
    const float* Wout = (const float*)d_in[9];
    const float* bout = (const float*)d_in[10];
    float* out = (float*)d_out;

    cudaFuncSetAttribute(lstm_seq_kernel,
                         cudaFuncAttributeMaxDynamicSharedMemorySize, SMEM_BYTES);
    lstm_seq_kernel<<<NBLK, 256, SMEM_BYTES>>>(
        x, Wih1, Whh1, bih1, bhh1, Wih2, Whh2, bih2, bhh2, Wout, bout, out);
}